// round 2
// baseline (speedup 1.0000x reference)
#include <cuda_runtime.h>
#include <math.h>

// Multi-head causal attention, fp32.
// q,k,v: [B,S,E] with E = H*D (head h occupies cols h*D..h*D+63)
// out:   [B,S,E]
// attn:  [B,H,S,S] (written only if the output buffer is large enough)

namespace {
constexpr int kB = 2, kS = 2048, kH = 16, kD = 64, kE = 1024;
constexpr int TQ = 64, TK = 64;
constexpr int NKT = kS / TK;          // 32 key tiles
constexpr float kScale = 0.125f;      // 1/sqrt(64)
constexpr int KVS = 68;               // smem stride for K^T / V tiles (16B-aligned, conflict-free)
constexpr int SMEM_FLOATS = 64 * 64   /* Qs */
                          + 64 * 64   /* Ps */
                          + 64 * KVS; /* KV  */
constexpr long long OUT_ELEMS  = (long long)kB * kS * kE;       // 4,194,304
constexpr long long ATTN_ELEMS = (long long)kB * kH * kS * kS;  // 134,217,728
}  // namespace

__global__ __launch_bounds__(256)
void attn_causal_kernel(const float* __restrict__ q,
                        const float* __restrict__ k,
                        const float* __restrict__ v,
                        float* __restrict__ out,
                        float* __restrict__ attn) {
    extern __shared__ float sm[];
    float* Qs = sm;                // [64][64]   Q tile (row-major, d contiguous)
    float* Ps = sm + 64 * 64;      // [64][64]   probability tile for PV GEMM
    float* KV = sm + 2 * 64 * 64;  // [64][KVS]  K tile transposed (Kt[d][c]) / V tile natural (V[k][d])
    __shared__ float mrow[64];
    __shared__ float lrow[64];

    const int tid = threadIdx.x;
    const int tx = tid & 15;       // 0..15 -> 4 columns each
    const int ty = tid >> 4;       // 0..15 -> 4 rows each
    const int r0 = ty * 4;
    const int c0 = tx * 4;

    const int qt = blockIdx.x;     // q tile index, 0..31
    const int bh = blockIdx.y;     // b*H + h, 0..31
    const int b  = bh >> 4;
    const int h  = bh & 15;

    const float* qbase = q + (long long)b * kS * kE + h * kD;
    const float* kbase = k + (long long)b * kS * kE + h * kD;
    const float* vbase = v + (long long)b * kS * kE + h * kD;
    float*       obase = out + (long long)b * kS * kE + h * kD;
    float*       abase = attn ? attn + (long long)bh * kS * kS : nullptr;

    // ---- load Q tile ----
    #pragma unroll
    for (int i = 0; i < 16; i++) {
        int e = tid + i * 256;        // 0..4095
        int r = e >> 6, d = e & 63;
        Qs[r * 64 + d] = qbase[(long long)(qt * 64 + r) * kE + d];
    }
    if (tid < 64) { mrow[tid] = -INFINITY; lrow[tid] = 0.f; }
    __syncthreads();

    // =========================================================
    // Phase 1: streaming row max (m) and sum-exp (l) over valid K tiles
    // =========================================================
    for (int kt = 0; kt <= qt; kt++) {
        // load K tile TRANSPOSED: KV[d][kr]
        #pragma unroll
        for (int i = 0; i < 16; i++) {
            int e = tid + i * 256;
            int kr = e >> 6, d = e & 63;
            KV[d * KVS + kr] = kbase[(long long)(kt * 64 + kr) * kE + d];
        }
        __syncthreads();

        // S = Q * K^T  (4x4 per thread)
        float acc[4][4] = {};
        #pragma unroll
        for (int d4 = 0; d4 < 64; d4 += 4) {
            float4 kv0 = *(const float4*)&KV[(d4 + 0) * KVS + c0];
            float4 kv1 = *(const float4*)&KV[(d4 + 1) * KVS + c0];
            float4 kv2 = *(const float4*)&KV[(d4 + 2) * KVS + c0];
            float4 kv3 = *(const float4*)&KV[(d4 + 3) * KVS + c0];
            #pragma unroll
            for (int i = 0; i < 4; i++) {
                float4 qv = *(const float4*)&Qs[(r0 + i) * 64 + d4];
                acc[i][0] += qv.x * kv0.x + qv.y * kv1.x + qv.z * kv2.x + qv.w * kv3.x;
                acc[i][1] += qv.x * kv0.y + qv.y * kv1.y + qv.z * kv2.y + qv.w * kv3.y;
                acc[i][2] += qv.x * kv0.z + qv.y * kv1.z + qv.z * kv2.z + qv.w * kv3.z;
                acc[i][3] += qv.x * kv0.w + qv.y * kv1.w + qv.z * kv2.w + qv.w * kv3.w;
            }
        }

        // scale + causal mask
        const int rq0 = qt * 64 + r0;
        const int ck0 = kt * 64 + c0;
        #pragma unroll
        for (int i = 0; i < 4; i++)
            #pragma unroll
            for (int j = 0; j < 4; j++) {
                float s = acc[i][j] * kScale;
                if (ck0 + j > rq0 + i) s = -INFINITY;
                acc[i][j] = s;
            }

        // row reductions across the 16 lanes owning this row group
        float mo[4], mn[4], se[4];
        #pragma unroll
        for (int i = 0; i < 4; i++) {
            float rm = fmaxf(fmaxf(acc[i][0], acc[i][1]), fmaxf(acc[i][2], acc[i][3]));
            #pragma unroll
            for (int off = 8; off > 0; off >>= 1)
                rm = fmaxf(rm, __shfl_xor_sync(0xffffffffu, rm, off, 16));
            mo[i] = mrow[r0 + i];
            mn[i] = fmaxf(mo[i], rm);
            float s = __expf(acc[i][0] - mn[i]) + __expf(acc[i][1] - mn[i]) +
                      __expf(acc[i][2] - mn[i]) + __expf(acc[i][3] - mn[i]);
            #pragma unroll
            for (int off = 8; off > 0; off >>= 1)
                s += __shfl_xor_sync(0xffffffffu, s, off, 16);
            se[i] = s;
        }
        __syncthreads();  // all mrow reads + KV reads done
        if (tx == 0) {
            #pragma unroll
            for (int i = 0; i < 4; i++) {
                lrow[r0 + i] = lrow[r0 + i] * __expf(mo[i] - mn[i]) + se[i];
                mrow[r0 + i] = mn[i];
            }
        }
    }
    __syncthreads();

    float mfin[4], lfin[4];
    #pragma unroll
    for (int i = 0; i < 4; i++) {
        mfin[i] = mrow[r0 + i];
        lfin[i] = 1.0f / lrow[r0 + i];
    }

    // =========================================================
    // Phase 2: recompute S, write normalized probs, accumulate O = P*V
    // =========================================================
    float oacc[4][4] = {};
    for (int kt = 0; kt <= qt; kt++) {
        #pragma unroll
        for (int i = 0; i < 16; i++) {
            int e = tid + i * 256;
            int kr = e >> 6, d = e & 63;
            KV[d * KVS + kr] = kbase[(long long)(kt * 64 + kr) * kE + d];
        }
        __syncthreads();

        float acc[4][4] = {};
        #pragma unroll
        for (int d4 = 0; d4 < 64; d4 += 4) {
            float4 kv0 = *(const float4*)&KV[(d4 + 0) * KVS + c0];
            float4 kv1 = *(const float4*)&KV[(d4 + 1) * KVS + c0];
            float4 kv2 = *(const float4*)&KV[(d4 + 2) * KVS + c0];
            float4 kv3 = *(const float4*)&KV[(d4 + 3) * KVS + c0];
            #pragma unroll
            for (int i = 0; i < 4; i++) {
                float4 qv = *(const float4*)&Qs[(r0 + i) * 64 + d4];
                acc[i][0] += qv.x * kv0.x + qv.y * kv1.x + qv.z * kv2.x + qv.w * kv3.x;
                acc[i][1] += qv.x * kv0.y + qv.y * kv1.y + qv.z * kv2.y + qv.w * kv3.y;
                acc[i][2] += qv.x * kv0.z + qv.y * kv1.z + qv.z * kv2.z + qv.w * kv3.z;
                acc[i][3] += qv.x * kv0.w + qv.y * kv1.w + qv.z * kv2.w + qv.w * kv3.w;
            }
        }

        const int rq0 = qt * 64 + r0;
        const int ck0 = kt * 64 + c0;
        float p[4][4];
        #pragma unroll
        for (int i = 0; i < 4; i++)
            #pragma unroll
            for (int j = 0; j < 4; j++) {
                bool valid = (ck0 + j) <= (rq0 + i);
                p[i][j] = valid ? __expf(acc[i][j] * kScale - mfin[i]) * lfin[i] : 0.0f;
            }

        // write attention probabilities
        if (abase) {
            #pragma unroll
            for (int i = 0; i < 4; i++) {
                float4 pv = make_float4(p[i][0], p[i][1], p[i][2], p[i][3]);
                *(float4*)&abase[(long long)(qt * 64 + r0 + i) * kS + kt * 64 + c0] = pv;
            }
        }
        __syncthreads();  // everyone done reading KV (K tile)

        // stage P into smem; load V tile (natural layout) into KV
        #pragma unroll
        for (int i = 0; i < 4; i++)
            *(float4*)&Ps[(r0 + i) * 64 + c0] = make_float4(p[i][0], p[i][1], p[i][2], p[i][3]);
        #pragma unroll
        for (int i = 0; i < 16; i++) {
            int e = tid + i * 256;
            int kr = e >> 6, d = e & 63;
            KV[kr * KVS + d] = vbase[(long long)(kt * 64 + kr) * kE + d];
        }
        __syncthreads();

        // O += P * V
        #pragma unroll
        for (int k4 = 0; k4 < 64; k4 += 4) {
            float4 vv0 = *(const float4*)&KV[(k4 + 0) * KVS + c0];
            float4 vv1 = *(const float4*)&KV[(k4 + 1) * KVS + c0];
            float4 vv2 = *(const float4*)&KV[(k4 + 2) * KVS + c0];
            float4 vv3 = *(const float4*)&KV[(k4 + 3) * KVS + c0];
            #pragma unroll
            for (int i = 0; i < 4; i++) {
                float4 pv = *(const float4*)&Ps[(r0 + i) * 64 + k4];
                oacc[i][0] += pv.x * vv0.x + pv.y * vv1.x + pv.z * vv2.x + pv.w * vv3.x;
                oacc[i][1] += pv.x * vv0.y + pv.y * vv1.y + pv.z * vv2.y + pv.w * vv3.y;
                oacc[i][2] += pv.x * vv0.z + pv.y * vv1.z + pv.z * vv2.z + pv.w * vv3.z;
                oacc[i][3] += pv.x * vv0.w + pv.y * vv1.w + pv.z * vv2.w + pv.w * vv3.w;
            }
        }
        __syncthreads();  // before next K tile overwrite
    }

    // write output tile
    #pragma unroll
    for (int i = 0; i < 4; i++) {
        float4 ov = make_float4(oacc[i][0], oacc[i][1], oacc[i][2], oacc[i][3]);
        *(float4*)&obase[(long long)(qt * 64 + r0 + i) * kE + c0] = ov;
    }

    // zero-fill masked (upper triangular) attention tiles
    if (abase) {
        const float4 z4 = make_float4(0.f, 0.f, 0.f, 0.f);
        for (int kt = qt + 1; kt < NKT; kt++) {
            #pragma unroll
            for (int i = 0; i < 4; i++) {
                int e4 = tid + i * 256;      // 0..1023 float4s
                int r  = e4 >> 4;            // 16 float4 per row
                int c4 = e4 & 15;
                *(float4*)&abase[(long long)(qt * 64 + r) * kS + kt * 64 + c4 * 4] = z4;
            }
        }
    }
}

extern "C" void kernel_launch(void* const* d_in, const int* in_sizes, int n_in,
                              void* d_out, int out_size) {
    const float* q = (const float*)d_in[0];
    const float* k = (const float*)d_in[1];
    const float* v = (const float*)d_in[2];
    // d_in[3] is the causal mask (deterministic tril) — applied analytically.
    float* out = (float*)d_out;

    float* attn = nullptr;
    if ((long long)out_size >= OUT_ELEMS + ATTN_ELEMS) {
        attn = out + OUT_ELEMS;  // tuple order: (out, attn)
    }

    const int smem_bytes = SMEM_FLOATS * (int)sizeof(float);  // 50176
    cudaFuncSetAttribute(attn_causal_kernel,
                         cudaFuncAttributeMaxDynamicSharedMemorySize, smem_bytes);

    dim3 grid(NKT, kB * kH);  // (q tiles, batch*heads)
    attn_causal_kernel<<<grid, 256, smem_bytes>>>(q, k, v, out, attn);
}

// round 4
// speedup vs baseline: 2.5544x; 2.5544x over previous
#include <cuda_runtime.h>
#include <cuda_bf16.h>
#include <math.h>
#include <stdint.h>

// ============================================================================
// Causal multi-head attention via mma.sync bf16 (hi/lo split), sm_103.
// q,k,v: [B,S,E] fp32, E=H*D, D=64. out: [B,S,E]. attn: [B,H,S,S].
// ============================================================================

namespace {
constexpr int kS = 2048, kE = 1024;
constexpr int NQT = 16;                       // 128-row q tiles
constexpr long long OUT_ELEMS  = 4194304LL;
constexpr long long ATTN_ELEMS = 134217728LL;

// smem strides (bf16 elements per row) — chosen for conflict-free ldmatrix
constexpr int QSTR = 72;    // 144B rows (Q, K tiles: [128][64])
constexpr int VSTR = 136;   // 272B rows (Vt: [64][128])
constexpr int PSTR = 136;   // 272B rows (P:  [128][128])

constexpr int OFF_QH = 0;
constexpr int OFF_QL = OFF_QH + 128 * QSTR * 2;   // 18432
constexpr int OFF_KH = OFF_QL + 128 * QSTR * 2;   // 36864
constexpr int OFF_KL = OFF_KH + 128 * QSTR * 2;   // 55296
constexpr int OFF_VH = OFF_KL + 128 * QSTR * 2;   // 73728
constexpr int OFF_VL = OFF_VH + 64 * VSTR * 2;    // 91136
constexpr int OFF_PH = OFF_VL + 64 * VSTR * 2;    // 108544
constexpr int OFF_PL = OFF_PH + 128 * PSTR * 2;   // 143360
constexpr int OFF_L  = OFF_PL + 128 * PSTR * 2;   // 178176
constexpr int SMEM_BYTES = OFF_L + 128 * 4;       // 178688
}  // namespace

// ---------------- low-level helpers ----------------
__device__ __forceinline__ uint32_t smem_u32(const void* p) {
    uint32_t a;
    asm("{ .reg .u64 t; cvta.to.shared.u64 t, %1; cvt.u32.u64 %0, t; }" : "=r"(a) : "l"(p));
    return a;
}
__device__ __forceinline__ void ldsm4(uint32_t r[4], uint32_t addr) {
    asm volatile("ldmatrix.sync.aligned.m8n8.x4.shared.b16 {%0,%1,%2,%3}, [%4];"
                 : "=r"(r[0]), "=r"(r[1]), "=r"(r[2]), "=r"(r[3]) : "r"(addr));
}
__device__ __forceinline__ void mma16816(float c[4], const uint32_t a[4],
                                         uint32_t b0, uint32_t b1) {
    asm("mma.sync.aligned.m16n8k16.row.col.f32.bf16.bf16.f32 "
        "{%0,%1,%2,%3}, {%4,%5,%6,%7}, {%8,%9}, {%0,%1,%2,%3};"
        : "+f"(c[0]), "+f"(c[1]), "+f"(c[2]), "+f"(c[3])
        : "r"(a[0]), "r"(a[1]), "r"(a[2]), "r"(a[3]), "r"(b0), "r"(b1));
}
__device__ __forceinline__ float bfr(float x) {             // bf16-rounded value
    return __bfloat162float(__float2bfloat16(x));
}
__device__ __forceinline__ uint32_t packbf(float lo_c, float hi_c) {  // {low addr, high addr}
    uint32_t r;
    asm("cvt.rn.bf16x2.f32 %0, %1, %2;" : "=r"(r) : "f"(hi_c), "f"(lo_c));
    return r;
}

// S = Q*K^T on warp strip (2m x 4n layout), 3-product bf16 split.
// Also used for the pass-2 recompute.
__device__ __forceinline__ void run_s_mma(float (&S)[4][4][4], uint32_t sb,
                                          int wm, int wn, int lane) {
    const int arow = lane & 15, akh = lane >> 4;
    const int brow = ((lane >> 4) & 1) * 8 + (lane & 7), bkh = (lane >> 3) & 1;
    #pragma unroll
    for (int kb = 0; kb < 4; kb++) {
        uint32_t ah[4][4], al[4][4];
        #pragma unroll
        for (int mb = 0; mb < 4; mb++) {
            uint32_t off = (uint32_t)(((wm * 64 + mb * 16 + arow) * QSTR + kb * 16 + akh * 8) * 2);
            ldsm4(ah[mb], sb + OFF_QH + off);
            ldsm4(al[mb], sb + OFF_QL + off);
        }
        #pragma unroll
        for (int np = 0; np < 2; np++) {
            uint32_t boff = (uint32_t)(((wn * 32 + np * 16 + brow) * QSTR + kb * 16 + bkh * 8) * 2);
            uint32_t bh[4], bl[4];
            ldsm4(bh, sb + OFF_KH + boff);
            ldsm4(bl, sb + OFF_KL + boff);
            #pragma unroll
            for (int mb = 0; mb < 4; mb++) {
                mma16816(S[mb][2 * np + 0], ah[mb], bh[0], bh[1]);
                mma16816(S[mb][2 * np + 0], al[mb], bh[0], bh[1]);
                mma16816(S[mb][2 * np + 0], ah[mb], bl[0], bl[1]);
                mma16816(S[mb][2 * np + 1], ah[mb], bh[2], bh[3]);
                mma16816(S[mb][2 * np + 1], al[mb], bh[2], bh[3]);
                mma16816(S[mb][2 * np + 1], ah[mb], bl[2], bl[3]);
            }
        }
    }
}

// ============================================================================

__global__ __launch_bounds__(256, 1)
void attn_mma_kernel(const float* __restrict__ q, const float* __restrict__ k,
                     const float* __restrict__ v, float* __restrict__ out,
                     float* __restrict__ attn) {
    extern __shared__ char smc[];
    const uint32_t sb = smem_u32(smc);
    float* lsm = (float*)(smc + OFF_L);

    const int tid = threadIdx.x;
    const int lane = tid & 31;
    const int wid = tid >> 5;
    const int g = lane >> 2, t = lane & 3;

    const int wm = wid >> 2, wn = wid & 3;     // S layout: 2m x 4n
    const int wm2 = wid >> 1, wn2 = wid & 1;   // PV layout: 4m x 2n

    const int qt = (NQT - 1) - blockIdx.x;     // heavy tiles first
    const int bh = blockIdx.y;
    const int b = bh >> 4, h = bh & 15;

    const float* qb = q + (long long)b * kS * kE + h * 64;
    const float* kb = k + (long long)b * kS * kE + h * 64;
    const float* vb = v + (long long)b * kS * kE + h * 64;
    float* ob = out + (long long)b * kS * kE + h * 64;
    float* ab = attn ? attn + (long long)bh * kS * kS : nullptr;

    // ---- load Q (x 1/8, hi/lo bf16 split) ----
    #pragma unroll
    for (int i = 0; i < 8; i++) {
        int e4 = tid + i * 256;
        int r = e4 >> 4, d4 = (e4 & 15) << 2;
        float4 x = *(const float4*)&qb[(long long)(qt * 128 + r) * kE + d4];
        x.x *= 0.125f; x.y *= 0.125f; x.z *= 0.125f; x.w *= 0.125f;
        float h0 = bfr(x.x), h1 = bfr(x.y), h2 = bfr(x.z), h3 = bfr(x.w);
        uint32_t off = (uint32_t)((r * QSTR + d4) * 2);
        *(uint32_t*)(smc + OFF_QH + off)     = packbf(h0, h1);
        *(uint32_t*)(smc + OFF_QH + off + 4) = packbf(h2, h3);
        *(uint32_t*)(smc + OFF_QL + off)     = packbf(x.x - h0, x.y - h1);
        *(uint32_t*)(smc + OFF_QL + off + 4) = packbf(x.z - h2, x.w - h3);
    }
    if (tid < 128) lsm[tid] = 0.0f;

    float lpart[8];
    #pragma unroll
    for (int i = 0; i < 8; i++) lpart[i] = 0.0f;
    float Oacc[2][4][4];
    #pragma unroll
    for (int a = 0; a < 2; a++)
        #pragma unroll
        for (int bb = 0; bb < 4; bb++)
            #pragma unroll
            for (int c = 0; c < 4; c++) Oacc[a][bb][c] = 0.0f;

    // =====================================================================
    // PASS 1
    // =====================================================================
    for (int kt = 0; kt <= qt; kt++) {
        // load K tile (hi/lo split)
        #pragma unroll
        for (int i = 0; i < 8; i++) {
            int e4 = tid + i * 256;
            int r = e4 >> 4, d4 = (e4 & 15) << 2;
            float4 x = *(const float4*)&kb[(long long)(kt * 128 + r) * kE + d4];
            float h0 = bfr(x.x), h1 = bfr(x.y), h2 = bfr(x.z), h3 = bfr(x.w);
            uint32_t off = (uint32_t)((r * QSTR + d4) * 2);
            *(uint32_t*)(smc + OFF_KH + off)     = packbf(h0, h1);
            *(uint32_t*)(smc + OFF_KH + off + 4) = packbf(h2, h3);
            *(uint32_t*)(smc + OFF_KL + off)     = packbf(x.x - h0, x.y - h1);
            *(uint32_t*)(smc + OFF_KL + off + 4) = packbf(x.z - h2, x.w - h3);
        }
        // load V tile transposed: Vt[d][key]
        #pragma unroll
        for (int i = 0; i < 8; i++) {
            int idx = tid + i * 256;
            int key = idx & 127, dg = idx >> 7;
            float4 x = *(const float4*)&vb[(long long)(kt * 128 + key) * kE + dg * 4];
            #pragma unroll
            for (int j = 0; j < 4; j++) {
                float val = (&x.x)[j];
                float hi = bfr(val);
                int d = dg * 4 + j;
                *(__nv_bfloat16*)(smc + OFF_VH + (d * VSTR + key) * 2) = __float2bfloat16(hi);
                *(__nv_bfloat16*)(smc + OFF_VL + (d * VSTR + key) * 2) = __float2bfloat16(val - hi);
            }
        }
        __syncthreads();

        // ---- S = Q*K^T ----
        float S[4][4][4];
        #pragma unroll
        for (int mb = 0; mb < 4; mb++)
            #pragma unroll
            for (int nb = 0; nb < 4; nb++)
                #pragma unroll
                for (int c = 0; c < 4; c++) S[mb][nb][c] = 0.0f;
        run_s_mma(S, sb, wm, wn, lane);

        // ---- epilogue: exp, l-partials, stage P hi/lo ----
        const bool full = (kt < qt);
        #pragma unroll
        for (int mb = 0; mb < 4; mb++) {
            const int rl = wm * 64 + mb * 16 + g;
            const int grl = qt * 128 + rl, grh = grl + 8;
            #pragma unroll
            for (int nb = 0; nb < 4; nb++) {
                const int c0 = kt * 128 + wn * 32 + nb * 8 + 2 * t;
                float* s = S[mb][nb];
                float e0 = __expf(s[0]), e1 = __expf(s[1]);
                float e2 = __expf(s[2]), e3 = __expf(s[3]);
                if (!full) {
                    if (c0     > grl) e0 = 0.0f;
                    if (c0 + 1 > grl) e1 = 0.0f;
                    if (c0     > grh) e2 = 0.0f;
                    if (c0 + 1 > grh) e3 = 0.0f;
                }
                lpart[mb * 2]     += e0 + e1;
                lpart[mb * 2 + 1] += e2 + e3;
                float h0 = bfr(e0), h1 = bfr(e1), h2 = bfr(e2), h3 = bfr(e3);
                uint32_t pl = (uint32_t)((rl * PSTR + wn * 32 + nb * 8 + 2 * t) * 2);
                uint32_t ph = (uint32_t)(((rl + 8) * PSTR + wn * 32 + nb * 8 + 2 * t) * 2);
                *(uint32_t*)(smc + OFF_PH + pl) = packbf(h0, h1);
                *(uint32_t*)(smc + OFF_PL + pl) = packbf(e0 - h0, e1 - h1);
                *(uint32_t*)(smc + OFF_PH + ph) = packbf(h2, h3);
                *(uint32_t*)(smc + OFF_PL + ph) = packbf(e2 - h2, e3 - h3);
            }
        }
        __syncthreads();

        // ---- O += P*V (warps 4m x 2n) ----
        {
            const int arow = lane & 15, akh = lane >> 4;
            const int brow = ((lane >> 4) & 1) * 8 + (lane & 7), bkh = (lane >> 3) & 1;
            #pragma unroll
            for (int kb8 = 0; kb8 < 8; kb8++) {
                uint32_t pah[2][4], pal[2][4];
                #pragma unroll
                for (int mb = 0; mb < 2; mb++) {
                    uint32_t off = (uint32_t)(((wm2 * 32 + mb * 16 + arow) * PSTR + kb8 * 16 + akh * 8) * 2);
                    ldsm4(pah[mb], sb + OFF_PH + off);
                    ldsm4(pal[mb], sb + OFF_PL + off);
                }
                #pragma unroll
                for (int np = 0; np < 2; np++) {
                    uint32_t boff = (uint32_t)(((wn2 * 32 + np * 16 + brow) * VSTR + kb8 * 16 + bkh * 8) * 2);
                    uint32_t vh[4], vl[4];
                    ldsm4(vh, sb + OFF_VH + boff);
                    ldsm4(vl, sb + OFF_VL + boff);
                    #pragma unroll
                    for (int mb = 0; mb < 2; mb++) {
                        mma16816(Oacc[mb][2 * np + 0], pah[mb], vh[0], vh[1]);
                        mma16816(Oacc[mb][2 * np + 0], pal[mb], vh[0], vh[1]);
                        mma16816(Oacc[mb][2 * np + 0], pah[mb], vl[0], vl[1]);
                        mma16816(Oacc[mb][2 * np + 1], pah[mb], vh[2], vh[3]);
                        mma16816(Oacc[mb][2 * np + 1], pal[mb], vh[2], vh[3]);
                        mma16816(Oacc[mb][2 * np + 1], pah[mb], vl[2], vl[3]);
                    }
                }
            }
        }
        __syncthreads();
    }

    // ---- reduce l: quad shuffle then shared atomics ----
    #pragma unroll
    for (int i = 0; i < 8; i++) {
        lpart[i] += __shfl_xor_sync(0xffffffffu, lpart[i], 1);
        lpart[i] += __shfl_xor_sync(0xffffffffu, lpart[i], 2);
    }
    if (t == 0) {
        #pragma unroll
        for (int i = 0; i < 8; i++)
            atomicAdd(&lsm[wm * 64 + (i >> 1) * 16 + (i & 1) * 8 + g], lpart[i]);
    }
    __syncthreads();
    if (tid < 128) lsm[tid] = 1.0f / lsm[tid];
    __syncthreads();

    // ---- write O (normalized) ----
    #pragma unroll
    for (int mb = 0; mb < 2; mb++) {
        const int rl = wm2 * 32 + mb * 16 + g, rh = rl + 8;
        const float ril = lsm[rl], rih = lsm[rh];
        #pragma unroll
        for (int nb = 0; nb < 4; nb++) {
            const int c0 = wn2 * 32 + nb * 8 + 2 * t;
            float* o = Oacc[mb][nb];
            *(float2*)&ob[(long long)(qt * 128 + rl) * kE + c0] = make_float2(o[0] * ril, o[1] * ril);
            *(float2*)&ob[(long long)(qt * 128 + rh) * kE + c0] = make_float2(o[2] * rih, o[3] * rih);
        }
    }

    // =====================================================================
    // PASS 2: recompute S, write normalized attn
    // =====================================================================
    if (ab) {
        for (int kt = 0; kt <= qt; kt++) {
            #pragma unroll
            for (int i = 0; i < 8; i++) {
                int e4 = tid + i * 256;
                int r = e4 >> 4, d4 = (e4 & 15) << 2;
                float4 x = *(const float4*)&kb[(long long)(kt * 128 + r) * kE + d4];
                float h0 = bfr(x.x), h1 = bfr(x.y), h2 = bfr(x.z), h3 = bfr(x.w);
                uint32_t off = (uint32_t)((r * QSTR + d4) * 2);
                *(uint32_t*)(smc + OFF_KH + off)     = packbf(h0, h1);
                *(uint32_t*)(smc + OFF_KH + off + 4) = packbf(h2, h3);
                *(uint32_t*)(smc + OFF_KL + off)     = packbf(x.x - h0, x.y - h1);
                *(uint32_t*)(smc + OFF_KL + off + 4) = packbf(x.z - h2, x.w - h3);
            }
            __syncthreads();

            float S[4][4][4];
            #pragma unroll
            for (int mb = 0; mb < 4; mb++)
                #pragma unroll
                for (int nb = 0; nb < 4; nb++)
                    #pragma unroll
                    for (int c = 0; c < 4; c++) S[mb][nb][c] = 0.0f;
            run_s_mma(S, sb, wm, wn, lane);

            const bool full = (kt < qt);
            #pragma unroll
            for (int mb = 0; mb < 4; mb++) {
                const int rl = wm * 64 + mb * 16 + g;
                const int grl = qt * 128 + rl, grh = grl + 8;
                const float ril = lsm[rl], rih = lsm[rl + 8];
                #pragma unroll
                for (int nb = 0; nb < 4; nb++) {
                    const int c0 = kt * 128 + wn * 32 + nb * 8 + 2 * t;
                    float* s = S[mb][nb];
                    float p0 = __expf(s[0]) * ril, p1 = __expf(s[1]) * ril;
                    float p2 = __expf(s[2]) * rih, p3 = __expf(s[3]) * rih;
                    if (!full) {
                        if (c0     > grl) p0 = 0.0f;
                        if (c0 + 1 > grl) p1 = 0.0f;
                        if (c0     > grh) p2 = 0.0f;
                        if (c0 + 1 > grh) p3 = 0.0f;
                    }
                    *(float2*)&ab[(long long)grl * kS + c0] = make_float2(p0, p1);
                    *(float2*)&ab[(long long)grh * kS + c0] = make_float2(p2, p3);
                }
            }
            __syncthreads();
        }

        // ---- zero-fill masked tiles (kt > qt) ----
        const float4 z4 = make_float4(0.f, 0.f, 0.f, 0.f);
        for (int kt2 = qt + 1; kt2 < NQT; kt2++) {
            #pragma unroll
            for (int i = 0; i < 16; i++) {
                int e4 = tid + i * 256;
                int row = e4 >> 5, c4 = (e4 & 31) << 2;
                *(float4*)&ab[(long long)(qt * 128 + row) * kS + kt2 * 128 + c4] = z4;
            }
        }
    }
}

extern "C" void kernel_launch(void* const* d_in, const int* in_sizes, int n_in,
                              void* d_out, int out_size) {
    const float* q = (const float*)d_in[0];
    const float* k = (const float*)d_in[1];
    const float* v = (const float*)d_in[2];
    float* out = (float*)d_out;

    float* attn = nullptr;
    if ((long long)out_size >= OUT_ELEMS + ATTN_ELEMS) attn = out + OUT_ELEMS;

    cudaFuncSetAttribute(attn_mma_kernel,
                         cudaFuncAttributeMaxDynamicSharedMemorySize, SMEM_BYTES);

    dim3 grid(NQT, 32);
    attn_mma_kernel<<<grid, 256, SMEM_BYTES>>>(q, k, v, out, attn);
}